// round 13
// baseline (speedup 1.0000x reference)
#include <cuda_runtime.h>
#include <cuda_bf16.h>
#include <cstdint>
#include <math.h>

#define B_    8
#define C_    192
#define C2_   384
#define HH_   128
#define WW_   128
#define HW_   16384
#define HEADS_ 4
#define CH_   48
#define NSLICE 32
#define TAPS  36
#define TPI   1024

// ---------------- scratch (device globals) ------------------------------------
__device__ float g_kv0[B_*C2_*HW_];
__device__ float g_kvd[B_*C2_*HW_];       // k rows 0..191, v rows 192..383
__device__ float g_q  [B_*C_*HW_];
__device__ float g_part[NSLICE*B_*HEADS_*CH_*CH_];
__device__ float g_attn[B_*HEADS_*CH_*CH_];
__device__ float g_nsq[2*NSLICE*B_*C_];
__device__ uint32_t g_kvwH[C2_*96],   g_kvwL[C2_*96];
__device__ uint32_t g_mwH[B_*C_*96],  g_mwL[B_*C_*96];
__device__ float    g_wq9[C_*C_*9];
__device__ uint32_t g_uwH[TAPS*C_*96], g_uwL[TAPS*C_*96];
__device__ float    g_vw[(long)B_*TAPS*C_*TPI];
__device__ float    g_wm[(long)B_*TAPS*C_*TPI];

// ---------------- helpers ------------------------------------------------------
__device__ __forceinline__ uint32_t s2u(const void* p){
    uint32_t a;
    asm("{ .reg .u64 t; cvta.to.shared.u64 t, %1; cvt.u32.u64 %0, t; }" : "=r"(a) : "l"(p));
    return a;
}
__device__ __forceinline__ void split2(float v0, float v1, uint32_t& hp, uint32_t& lp){
    __nv_bfloat16 h0 = __float2bfloat16_rn(v0);
    __nv_bfloat16 h1 = __float2bfloat16_rn(v1);
    __nv_bfloat16 l0 = __float2bfloat16_rn(v0 - __bfloat162float(h0));
    __nv_bfloat16 l1 = __float2bfloat16_rn(v1 - __bfloat162float(h1));
    hp = (uint32_t)__bfloat16_as_ushort(h0) | ((uint32_t)__bfloat16_as_ushort(h1) << 16);
    lp = (uint32_t)__bfloat16_as_ushort(l0) | ((uint32_t)__bfloat16_as_ushort(l1) << 16);
}
__device__ __forceinline__ void ldsm4(uint32_t& r0, uint32_t& r1, uint32_t& r2,
                                      uint32_t& r3, uint32_t addr){
    asm volatile("ldmatrix.sync.aligned.m8n8.x4.shared.b16 {%0,%1,%2,%3}, [%4];"
                 : "=r"(r0), "=r"(r1), "=r"(r2), "=r"(r3) : "r"(addr));
}

// ---------------- weight preps -------------------------------------------------
__global__ void prep_kvw_kernel(const float* __restrict__ kv_w){
    int idx = blockIdx.x * 256 + threadIdx.x;
    int oc = idx / 96, c = idx % 96;
    uint32_t hp, lp;
    split2(kv_w[oc*C_ + 2*c], kv_w[oc*C_ + 2*c + 1], hp, lp);
    g_kvwH[idx] = hp; g_kvwL[idx] = lp;
}
__global__ void __launch_bounds__(192) prep_qw_kernel(
        const float* __restrict__ q_dw_w, const float* __restrict__ q_w){
    __shared__ float buf[3 * C_];
    const int o = blockIdx.x, ty = blockIdx.y, tid = threadIdx.x;
    #pragma unroll
    for (int j = 0; j < 3; j++)
        buf[tid * 3 + j] = q_dw_w[(o * C_ + tid) * 9 + ty * 3 + j];
    __syncthreads();
    float s[3] = {};
    const int i = tid;
    for (int m = 0; m < C_; m++){
        float qv = q_w[m * C_ + i];
        #pragma unroll
        for (int j = 0; j < 3; j++) s[j] = fmaf(buf[m * 3 + j], qv, s[j]);
    }
    #pragma unroll
    for (int j = 0; j < 3; j++)
        g_wq9[((long)o * 9 + ty * 3 + j) * C_ + i] = s[j];
}
__global__ void prep_mw_kernel(const float* __restrict__ projw){
    int idx = blockIdx.x * 256 + threadIdx.x;
    int c = idx % 96;
    int o = (idx / 96) % C_;
    int b = idx / (96 * C_);
    float sv[2];
    #pragma unroll
    for (int j = 0; j < 2; j++){
        int k = 2*c + j;
        int h = k / CH_, dl = k % CH_;
        const float* aw = &g_attn[((b * HEADS_ + h) * CH_) * CH_ + dl];
        const float* pw = &projw[o * C_ + h * CH_];
        float s = 0.f;
        for (int cc = 0; cc < CH_; cc++) s = fmaf(pw[cc], aw[cc * CH_], s);
        sv[j] = s;
    }
    uint32_t hp, lp;
    split2(sv[0], sv[1], hp, lp);
    g_mwH[idx] = hp; g_mwL[idx] = lp;
}

// ---------------- winograd weight transform: U = G W G^T -----------------------
__global__ void __launch_bounds__(96) wino_wt_kernel(){
    const int o = blockIdx.x, j = threadIdx.x;
    float Ua[36], Ub[36];
    #pragma unroll
    for (int half = 0; half < 2; half++){
        float* U = half ? Ub : Ua;
        int i = 2*j + half;
        float w[3][3];
        #pragma unroll
        for (int r = 0; r < 3; r++)
            #pragma unroll
            for (int c = 0; c < 3; c++)
                w[r][c] = g_wq9[((long)o*9 + r*3 + c)*C_ + i];
        float gw[6][3];
        #pragma unroll
        for (int c = 0; c < 3; c++){
            gw[0][c] = 0.25f*w[0][c];
            gw[1][c] = (-w[0][c]-w[1][c]-w[2][c])*(1.f/6.f);
            gw[2][c] = (-w[0][c]+w[1][c]-w[2][c])*(1.f/6.f);
            gw[3][c] = w[0][c]*(1.f/24.f) + w[1][c]*(1.f/12.f) + w[2][c]*(1.f/6.f);
            gw[4][c] = w[0][c]*(1.f/24.f) - w[1][c]*(1.f/12.f) + w[2][c]*(1.f/6.f);
            gw[5][c] = w[2][c];
        }
        #pragma unroll
        for (int r = 0; r < 6; r++){
            U[r*6+0] = 0.25f*gw[r][0];
            U[r*6+1] = (-gw[r][0]-gw[r][1]-gw[r][2])*(1.f/6.f);
            U[r*6+2] = (-gw[r][0]+gw[r][1]-gw[r][2])*(1.f/6.f);
            U[r*6+3] = gw[r][0]*(1.f/24.f) + gw[r][1]*(1.f/12.f) + gw[r][2]*(1.f/6.f);
            U[r*6+4] = gw[r][0]*(1.f/24.f) - gw[r][1]*(1.f/12.f) + gw[r][2]*(1.f/6.f);
            U[r*6+5] = gw[r][2];
        }
    }
    #pragma unroll
    for (int tp = 0; tp < 36; tp++){
        uint32_t hp, lp;
        split2(Ua[tp], Ub[tp], hp, lp);
        g_uwH[(long)tp*C_*96 + o*96 + j] = hp;
        g_uwL[(long)tp*C_*96 + o*96 + j] = lp;
    }
}

// ---------------- winograd input transform (ALU-lean, coalesced) ----------------
__global__ void __launch_bounds__(256) wino_in_kernel(const float* __restrict__ y){
    __shared__ float inS[8][6][132];
    const int TY  = blockIdx.x;
    const int ic0 = blockIdx.y * 8;
    const int b   = blockIdx.z;
    const int tid = threadIdx.x;
    const int wrp = tid >> 5, lane = tid & 31;
    {
        const int gy0 = 4*TY - 1;
        #pragma unroll
        for (int rr = 0; rr < 6; rr++){
            int rowid = wrp + rr * 8;
            int ic = rowid / 6, r = rowid % 6;
            int gy = gy0 + r;
            const float* src = y + ((long)(b*C_ + ic0 + ic))*HW_ + gy*WW_;
            bool rowok = (unsigned)gy < 128u;
            float* dst = &inS[ic][r][0];
            #pragma unroll
            for (int j = 0; j < 5; j++){
                int col = lane + j*32 - 1;
                if (j < 4 || col < 131){
                    float v = 0.f;
                    if (rowok && (unsigned)col < 128u) v = src[col];
                    if (col + 1 < 132) dst[col + 1] = v;
                }
            }
        }
    }
    __syncthreads();
    const int tx  = lane;
    const int icl = wrp;
    float vv[36];
    {
        float d[6][6];
        #pragma unroll
        for (int r = 0; r < 6; r++)
            #pragma unroll
            for (int c = 0; c < 6; c++)
                d[r][c] = inS[icl][r][4*tx + c];
        float t[6][6];
        #pragma unroll
        for (int c = 0; c < 6; c++){
            t[0][c] =  4.f*d[0][c] - 5.f*d[2][c] + d[4][c];
            t[1][c] = -4.f*d[1][c] - 4.f*d[2][c] + d[3][c] + d[4][c];
            t[2][c] =  4.f*d[1][c] - 4.f*d[2][c] - d[3][c] + d[4][c];
            t[3][c] = -2.f*d[1][c] - d[2][c] + 2.f*d[3][c] + d[4][c];
            t[4][c] =  2.f*d[1][c] - d[2][c] - 2.f*d[3][c] + d[4][c];
            t[5][c] =  4.f*d[1][c] - 5.f*d[3][c] + d[5][c];
        }
        #pragma unroll
        for (int r = 0; r < 6; r++){
            vv[r*6+0] =  4.f*t[r][0] - 5.f*t[r][2] + t[r][4];
            vv[r*6+1] = -4.f*t[r][1] - 4.f*t[r][2] + t[r][3] + t[r][4];
            vv[r*6+2] =  4.f*t[r][1] - 4.f*t[r][2] - t[r][3] + t[r][4];
            vv[r*6+3] = -2.f*t[r][1] - t[r][2] + 2.f*t[r][3] + t[r][4];
            vv[r*6+4] =  2.f*t[r][1] - t[r][2] - 2.f*t[r][3] + t[r][4];
            vv[r*6+5] =  4.f*t[r][1] - 5.f*t[r][3] + t[r][5];
        }
    }
    float* p = g_vw + (((long)(b*TAPS))*C_ + (ic0 + icl))*TPI + TY*32 + tx;
    #pragma unroll
    for (int tp = 0; tp < 36; tp++){
        *p = vv[tp];
        p += (long)C_ * TPI;
    }
}

// ---------------- winograd output transform ------------------------------------
__global__ void __launch_bounds__(128) wino_out_kernel(){
    const int tb = blockIdx.x, oc = blockIdx.y, b = blockIdx.z;
    const int tile = tb*128 + threadIdx.x;
    float m[36];
    const float* p = g_wm + (((long)(b*TAPS))*C_ + oc)*TPI + tile;
    #pragma unroll
    for (int tp = 0; tp < 36; tp++){
        m[tp] = *p;
        p += (long)C_ * TPI;
    }
    float t[4][6];
    #pragma unroll
    for (int c = 0; c < 6; c++){
        float m0=m[c], m1=m[6+c], m2=m[12+c], m3=m[18+c], m4=m[24+c], m5=m[30+c];
        t[0][c] = m0+m1+m2+m3+m4;
        t[1][c] = m1-m2+2.f*m3-2.f*m4;
        t[2][c] = m1+m2+4.f*m3+4.f*m4;
        t[3][c] = m1-m2+8.f*m3-8.f*m4+m5;
    }
    int ty = tile >> 5, tx = tile & 31;
    float* op = &g_q[((long)(b*C_ + oc))*HW_ + (4*ty)*WW_ + 4*tx];
    #pragma unroll
    for (int r = 0; r < 4; r++){
        float o0 = t[r][0]+t[r][1]+t[r][2]+t[r][3]+t[r][4];
        float o1 = t[r][1]-t[r][2]+2.f*t[r][3]-2.f*t[r][4];
        float o2 = t[r][1]+t[r][2]+4.f*t[r][3]+4.f*t[r][4];
        float o3 = t[r][1]-t[r][2]+8.f*t[r][3]-8.f*t[r][4]+t[r][5];
        *(float4*)&op[r*WW_] = make_float4(o0,o1,o2,o3);
    }
}

// ---------------- 3-term bf16 mma.sync GEMM, fp32 A-side, M128 x N192 ----------
#define ROWB 80
#define KPW  20
#define AHB  (128 * ROWB)
#define BHB  (192 * ROWB)
#define STG  (2*AHB + 2*BHB)       // 51200
#define TG_SMEM (3*STG)            // 153600

template<int MODE>
__global__ void __launch_bounds__(512, 1) mma_gemm_kernel(
    const float* __restrict__ A, long aBS, int aRow,
    const uint32_t* __restrict__ BH, const uint32_t* __restrict__ BL, long bBS,
    int bRow, int NG, float* __restrict__ Out, long oBS, int oRow)
{
    extern __shared__ char smem[];
    const uint32_t sb = s2u(smem);
    const int tid = threadIdx.x;
    const int b = blockIdx.z;
    const int pBase = blockIdx.x * 128;
    const int nBase = blockIdx.y * 192;
    const float* Ab = A + (long)b * aBS;
    const long bsel2 = (MODE == 2) ? (long)(b % TAPS) : (long)b;
    const uint32_t* BHb = BH + bsel2 * bBS + (long)nBase * bRow;
    const uint32_t* BLb = BL + bsel2 * bBS + (long)nBase * bRow;

    const int lane = tid & 31, wid = tid >> 5;
    const int wm = (wid & 3) * 32;
    const int wn = (wid >> 2) * 48;
    const int g8 = lane >> 2, tig = lane & 3;
    const uint32_t arow = (lane & 7) + ((lane >> 3) & 1) * 8;
    const uint32_t acol = ((lane >> 4) & 1) * 4;
    const uint32_t brow = (lane & 7) + ((lane >> 4) & 1) * 8;
    const uint32_t bcol = ((lane >> 3) & 1) * 4;
    const int am = tid & 127, akp = tid >> 7;

    float acc[2][6][4];
    #pragma unroll
    for (int a = 0; a < 2; a++)
        #pragma unroll
        for (int n = 0; n < 6; n++)
            #pragma unroll
            for (int c = 0; c < 4; c++) acc[a][n][c] = 0.f;

    float rbuf[2][8];
    auto ldA = [&](int g, float* rb){
        const float* base = Ab + pBase + am;
        #pragma unroll
        for (int j = 0; j < 4; j++){
            int k = g*32 + 2*(akp + j*4);
            const float* p = base + (long)k * aRow;
            rb[2*j]   = __ldg(p);
            rb[2*j+1] = __ldg(p + aRow);
        }
    };
    auto stA = [&](int sel, const float* rb){
        uint32_t abuf = sb + (uint32_t)sel*STG + am*ROWB;
        #pragma unroll
        for (int j = 0; j < 4; j++){
            int kp = akp + j*4;
            uint32_t hp, lp; split2(rb[2*j], rb[2*j+1], hp, lp);
            asm volatile("st.shared.b32 [%0], %1;" :: "r"(abuf + kp*4), "r"(hp));
            asm volatile("st.shared.b32 [%0], %1;" :: "r"(abuf + AHB + kp*4), "r"(lp));
        }
    };
    auto stageB = [&](int g, int sel){
        const uint32_t bhbuf = sb + sel * STG + 2 * AHB;
        const uint32_t blbuf = bhbuf + BHB;
        #pragma unroll
        for (int i = 0; i < 3; i++){
            int idx = tid + i * 512;
            int n = idx >> 3, r = idx & 7;
            int arr = r >> 2, c16 = r & 3;
            uint32_t sa = (arr ? blbuf : bhbuf) + n * ROWB + c16 * 16;
            const uint32_t* gp = (arr ? BLb : BHb) + (long)n * bRow + g * 16 + c16 * 4;
            asm volatile("cp.async.cg.shared.global [%0], [%1], 16;" :: "r"(sa), "l"(gp) : "memory");
        }
        asm volatile("cp.async.commit_group;" ::: "memory");
    };

    ldA(0, rbuf[0]);
    stageB(0, 0);
    ldA(1, rbuf[1]);
    stageB(1, 1);
    stA(0, rbuf[0]);
    for (int g = 0; g < NG; g++){
        const int sel = g % 3;
        if (g + 1 < NG) stA((g + 1) % 3, rbuf[(g + 1) % 2]);
        if (g + 2 < NG){
            ldA(g + 2, rbuf[(g + 2) % 2]);
            stageB(g + 2, (g + 2) % 3);
            asm volatile("cp.async.wait_group 2;" ::: "memory");
        } else if (g + 1 < NG){
            asm volatile("cp.async.wait_group 1;" ::: "memory");
        } else {
            asm volatile("cp.async.wait_group 0;" ::: "memory");
        }
        __syncthreads();
        const uint32_t abase  = sb + sel * STG;
        const uint32_t albase = abase + AHB;
        const uint32_t bhbase = abase + 2 * AHB;
        const uint32_t blbase = bhbase + BHB;
        #pragma unroll
        for (int ks = 0; ks < 2; ks++){
            uint32_t bh[6][2], bl[6][2];
            #pragma unroll
            for (int j = 0; j < 3; j++){
                uint32_t off = (uint32_t)((wn + j * 16 + brow) * ROWB + (ks * 8 + bcol) * 4);
                ldsm4(bh[2*j][0], bh[2*j][1], bh[2*j+1][0], bh[2*j+1][1], bhbase + off);
                ldsm4(bl[2*j][0], bl[2*j][1], bl[2*j+1][0], bl[2*j+1][1], blbase + off);
            }
            #pragma unroll
            for (int mt = 0; mt < 2; mt++){
                uint32_t off = (uint32_t)((wm + mt * 16 + arow) * ROWB + (ks * 8 + acol) * 4);
                uint32_t ah0, ah1, ah2, ah3, al0, al1, al2, al3;
                ldsm4(ah0, ah1, ah2, ah3, abase + off);
                ldsm4(al0, al1, al2, al3, albase + off);
                #pragma unroll
                for (int nt = 0; nt < 6; nt++){
                    asm volatile(
                        "mma.sync.aligned.m16n8k16.row.col.f32.bf16.bf16.f32 "
                        "{%0,%1,%2,%3}, {%4,%5,%6,%7}, {%8,%9}, {%0,%1,%2,%3};"
                        : "+f"(acc[mt][nt][0]), "+f"(acc[mt][nt][1]),
                          "+f"(acc[mt][nt][2]), "+f"(acc[mt][nt][3])
                        : "r"(ah0), "r"(ah1), "r"(ah2), "r"(ah3),
                          "r"(bh[nt][0]), "r"(bh[nt][1]));
                    asm volatile(
                        "mma.sync.aligned.m16n8k16.row.col.f32.bf16.bf16.f32 "
                        "{%0,%1,%2,%3}, {%4,%5,%6,%7}, {%8,%9}, {%0,%1,%2,%3};"
                        : "+f"(acc[mt][nt][0]), "+f"(acc[mt][nt][1]),
                          "+f"(acc[mt][nt][2]), "+f"(acc[mt][nt][3])
                        : "r"(ah0), "r"(ah1), "r"(ah2), "r"(ah3),
                          "r"(bl[nt][0]), "r"(bl[nt][1]));
                    asm volatile(
                        "mma.sync.aligned.m16n8k16.row.col.f32.bf16.bf16.f32 "
                        "{%0,%1,%2,%3}, {%4,%5,%6,%7}, {%8,%9}, {%0,%1,%2,%3};"
                        : "+f"(acc[mt][nt][0]), "+f"(acc[mt][nt][1]),
                          "+f"(acc[mt][nt][2]), "+f"(acc[mt][nt][3])
                        : "r"(al0), "r"(al1), "r"(al2), "r"(al3),
                          "r"(bh[nt][0]), "r"(bh[nt][1]));
                }
            }
        }
        __syncthreads();
    }

    float* Cs = (float*)smem;
    #pragma unroll
    for (int mt = 0; mt < 2; mt++)
        #pragma unroll
        for (int nt = 0; nt < 6; nt++){
            int m0 = wm + mt * 16 + g8;
            int n0 = wn + nt * 8 + tig * 2;
            Cs[n0 * 132 + m0]           = acc[mt][nt][0];
            Cs[(n0 + 1) * 132 + m0]     = acc[mt][nt][1];
            Cs[n0 * 132 + m0 + 8]       = acc[mt][nt][2];
            Cs[(n0 + 1) * 132 + m0 + 8] = acc[mt][nt][3];
        }
    __syncthreads();
    float* Ob = Out + (long)b * oBS;
    #pragma unroll
    for (int i = 0; i < 12; i++){
        int idx = tid + i * 512;
        int n = idx >> 5, c4 = idx & 31;
        *(float4*)&Ob[(long)(nBase + n) * oRow + pBase + c4 * 4] =
            *(float4*)&Cs[n * 132 + c4 * 4];
    }
}

// ---------------- depthwise 3x3, smem-tiled ------------------------------------
__global__ void __launch_bounds__(256) dw_kernel(const float* __restrict__ dww) {
    __shared__ float tile[34][128];
    __shared__ float ws[9];
    const int b = blockIdx.z, c = blockIdx.y, rb = blockIdx.x * 32;
    const int tid = threadIdx.x;
    if (tid < 9) ws[tid] = dww[c * 9 + tid];
    const float* ip = &g_kv0[((long)(b * C2_ + c)) * HW_];
    for (int idx = tid; idx < 34 * 128; idx += 256){
        int lr = idx >> 7, col = idx & 127;
        int gy = rb - 1 + lr;
        tile[lr][col] = ((unsigned)gy < 128u) ? ip[gy * 128 + col] : 0.f;
    }
    __syncthreads();
    const int lrow = tid >> 3, c0 = (tid & 7) * 16;
    float wv[3][18];
    #pragma unroll
    for (int dy = 0; dy < 3; dy++){
        const float* tr = tile[lrow + dy];
        wv[dy][0]  = (c0 > 0) ? tr[c0 - 1] : 0.f;
        #pragma unroll
        for (int q = 0; q < 4; q++){
            float4 v = *(const float4*)&tr[c0 + q * 4];
            wv[dy][1 + q*4] = v.x; wv[dy][2 + q*4] = v.y;
            wv[dy][3 + q*4] = v.z; wv[dy][4 + q*4] = v.w;
        }
        wv[dy][17] = (c0 + 16 < 128) ? tr[c0 + 16] : 0.f;
    }
    float o[16];
    #pragma unroll
    for (int cc = 0; cc < 16; cc++){
        float a = 0.f;
        #pragma unroll
        for (int dy = 0; dy < 3; dy++)
            #pragma unroll
            for (int dx = 0; dx < 3; dx++)
                a = fmaf(ws[dy * 3 + dx], wv[dy][cc + dx], a);
        o[cc] = a;
    }
    float* op = &g_kvd[((long)(b * C2_ + c)) * HW_ + (rb + lrow) * 128 + c0];
    #pragma unroll
    for (int q = 0; q < 4; q++)
        *(float4*)&op[q * 4] = make_float4(o[q*4], o[q*4+1], o[q*4+2], o[q*4+3]);
}

// ---------------- QK^T partial dots + fused sumsq (float4, NSLICE=32) ----------
__global__ __launch_bounds__(256) void attn_dot_kernel() {
    __shared__ float qS[CH_ * 68];
    __shared__ float kS[CH_ * 68];
    __shared__ float srq[CH_], srk[CH_];
    const int sl = blockIdx.x, h = blockIdx.y, b = blockIdx.z;
    const int tid = threadIdx.x;
    const int wrp = tid >> 5, lane = tid & 31;
    const int c0 = (tid >> 4) * 3, d0 = (tid & 15) * 3;
    float acc[3][3] = {};
    float sqq[3] = {}, sqk[3] = {};
    const float* qbase = &g_q[((long)(b * C_) + h * CH_) * HW_];
    const float* kbase = &g_kvd[((long)(b * C2_) + h * CH_) * HW_];
    const int n0 = sl * (HW_ / NSLICE);          // 512 per slice
    for (int chn = 0; chn < HW_ / NSLICE; chn += 64) {
        #pragma unroll
        for (int i = 0; i < 3; i++){
            int idx = tid + i * 256;             // 768 float4 units: 48 rows x 16
            int r = idx >> 4, c4 = idx & 15;
            float4 vq = *(const float4*)&qbase[(long)r * HW_ + n0 + chn + c4 * 4];
            float4 vk = *(const float4*)&kbase[(long)r * HW_ + n0 + chn + c4 * 4];
            *(float4*)&qS[r * 68 + c4 * 4] = vq;
            *(float4*)&kS[r * 68 + c4 * 4] = vk;
            sqq[i] = fmaf(vq.x, vq.x, fmaf(vq.y, vq.y, fmaf(vq.z, vq.z, fmaf(vq.w, vq.w, sqq[i]))));
            sqk[i] = fmaf(vk.x, vk.x, fmaf(vk.y, vk.y, fmaf(vk.z, vk.z, fmaf(vk.w, vk.w, sqk[i]))));
        }
        __syncthreads();
        #pragma unroll
        for (int n = 0; n < 64; n += 4) {
            float4 qv[3], kv[3];
            #pragma unroll
            for (int i = 0; i < 3; i++) qv[i] = *(const float4*)&qS[(c0 + i) * 68 + n];
            #pragma unroll
            for (int i = 0; i < 3; i++) kv[i] = *(const float4*)&kS[(d0 + i) * 68 + n];
            #pragma unroll
            for (int i = 0; i < 3; i++)
                #pragma unroll
                for (int j = 0; j < 3; j++) {
                    acc[i][j] = fmaf(qv[i].x, kv[j].x, acc[i][j]);
                    acc[i][j] = fmaf(qv[i].y, kv[j].y, acc[i][j]);
                    acc[i][j] = fmaf(qv[i].z, kv[j].z, acc[i][j]);
                    acc[i][j] = fmaf(qv[i].w, kv[j].w, acc[i][j]);
                }
        }
        __syncthreads();
    }
    // reduce sumsq: (warp, i) owns rows 2*wrp+16*i and +1 (lanes 0-15 / 16-31)
    #pragma unroll
    for (int i = 0; i < 3; i++){
        float vq = sqq[i], vk = sqk[i];
        #pragma unroll
        for (int off = 8; off; off >>= 1){
            vq += __shfl_xor_sync(0xffffffffu, vq, off);
            vk += __shfl_xor_sync(0xffffffffu, vk, off);
        }
        if ((lane & 15) == 0){
            int row = 2 * wrp + 16 * i + (lane >> 4);
            srq[row] = vq; srk[row] = vk;
        }
    }
    __syncthreads();
    if (tid < CH_){
        g_nsq[((long)sl * B_ + b) * C_ + h * CH_ + tid] = srq[tid];
        g_nsq[(long)NSLICE * B_ * C_ + ((long)sl * B_ + b) * C_ + h * CH_ + tid] = srk[tid];
    }
    float* outp = &g_part[(((long)sl * B_ + b) * HEADS_ + h) * CH_ * CH_];
    #pragma unroll
    for (int i = 0; i < 3; i++)
        #pragma unroll
        for (int j = 0; j < 3; j++)
            outp[(c0 + i) * CH_ + d0 + j] = acc[i][j];
}

// ---------------- scale + softmax ---------------------------------------------
__global__ void softmax_kernel(const float* __restrict__ temp) {
    __shared__ float ikS[CH_];
    const int h = blockIdx.x & 3, b = blockIdx.x >> 2;
    const int c = threadIdx.x;
    if (c < CH_){
        float s = 0.f;
        for (int sl = 0; sl < NSLICE; sl++)
            s += g_nsq[(long)NSLICE * B_ * C_ + ((long)sl * B_ + b) * C_ + h * CH_ + c];
        ikS[c] = 1.0f / fmaxf(sqrtf(s), 1e-12f);
    }
    __syncthreads();
    if (c >= CH_) return;
    float sq = 0.f;
    for (int sl = 0; sl < NSLICE; sl++)
        sq += g_nsq[((long)sl * B_ + b) * C_ + h * CH_ + c];
    const float iq = 1.0f / fmaxf(sqrtf(sq), 1e-12f);
    const float t = temp[h] * logf((float)CH_);
    float row[CH_];
    float m = -1e30f;
    for (int d = 0; d < CH_; d++) {
        float s = 0.f;
        for (int sl = 0; sl < NSLICE; sl++)
            s += g_part[(((long)sl * B_ + b) * HEADS_ + h) * CH_ * CH_ + c * CH_ + d];
        row[d] = s * iq * ikS[d] * t;
        m = fmaxf(m, row[d]);
    }
    float sum = 0.f;
    for (int d = 0; d < CH_; d++) {
        row[d] = expf(row[d] - m);
        sum += row[d];
    }
    float inv = 1.0f / sum;
    for (int d = 0; d < CH_; d++)
        g_attn[((b * HEADS_ + h) * CH_ + c) * CH_ + d] = row[d] * inv;
}

// ---------------- launch ------------------------------------------------------
extern "C" void kernel_launch(void* const* d_in, const int* in_sizes, int n_in,
                              void* d_out, int out_size) {
    const float* x       = (const float*)d_in[0];
    const float* y       = (const float*)d_in[1];
    const float* kv_w    = (const float*)d_in[2];
    const float* kv_dw_w = (const float*)d_in[3];
    const float* q_w     = (const float*)d_in[4];
    const float* q_dw_w  = (const float*)d_in[5];
    const float* proj_w  = (const float*)d_in[6];
    const float* temp    = (const float*)d_in[7];
    float* out = (float*)d_out;

    void *p_kv0, *p_kvd, *p_q, *p_kwh, *p_kwl, *p_mwh, *p_mwl;
    void *p_uwh, *p_uwl, *p_vw, *p_wm;
    cudaGetSymbolAddress(&p_kv0, g_kv0);
    cudaGetSymbolAddress(&p_kvd, g_kvd);
    cudaGetSymbolAddress(&p_q,   g_q);
    cudaGetSymbolAddress(&p_kwh, g_kvwH); cudaGetSymbolAddress(&p_kwl, g_kvwL);
    cudaGetSymbolAddress(&p_mwh, g_mwH);  cudaGetSymbolAddress(&p_mwl, g_mwL);
    cudaGetSymbolAddress(&p_uwh, g_uwH);  cudaGetSymbolAddress(&p_uwl, g_uwL);
    cudaGetSymbolAddress(&p_vw,  g_vw);   cudaGetSymbolAddress(&p_wm,  g_wm);

    cudaFuncSetAttribute(mma_gemm_kernel<0>, cudaFuncAttributeMaxDynamicSharedMemorySize, TG_SMEM);
    cudaFuncSetAttribute(mma_gemm_kernel<2>, cudaFuncAttributeMaxDynamicSharedMemorySize, TG_SMEM);

    prep_qw_kernel<<<dim3(C_, 3), 192>>>(q_dw_w, q_w);                                 // #1
    wino_wt_kernel<<<C_, 96>>>();                                                      // #2
    wino_in_kernel<<<dim3(32, 24, B_), 256>>>(y);                                      // #3

    // winograd batched per-tap GEMM                              — launch #4 (ncu slot)
    mma_gemm_kernel<2><<<dim3(TPI / 128, 1, B_ * TAPS), 512, TG_SMEM>>>(
        (const float*)p_vw, (long)C_ * TPI, TPI,
        (const uint32_t*)p_uwh, (const uint32_t*)p_uwl, (long)C_ * 96, 96, 6,
        (float*)p_wm, (long)C_ * TPI, TPI);

    prep_kvw_kernel<<<(C2_ * 96) / 256, 256>>>(kv_w);                                  // #5

    // kv 1x1: A = x fp32 direct; N=384 as 2 chunks of 192                             // #6
    mma_gemm_kernel<0><<<dim3(HW_ / 128, 2, B_), 512, TG_SMEM>>>(
        x, (long)C_ * HW_, HW_,
        (const uint32_t*)p_kwh, (const uint32_t*)p_kwl, 0L, 96, 6,
        (float*)p_kv0, (long)C2_ * HW_, HW_);

    dw_kernel<<<dim3(HH_ / 32, C2_, B_), 256>>>(kv_dw_w);                              // #7
    wino_out_kernel<<<dim3(TPI / 128, C_, B_), 128>>>();                               // #8

    attn_dot_kernel<<<dim3(NSLICE, HEADS_, B_), 256>>>();                              // #9
    softmax_kernel<<<B_ * HEADS_, 64>>>(temp);                                         // #10
    prep_mw_kernel<<<(B_ * C_ * 96) / 256, 256>>>(proj_w);                             // #11

    // fused (proj @ attn) @ v -> out                                                  // #12
    mma_gemm_kernel<0><<<dim3(HW_ / 128, 1, B_), 512, TG_SMEM>>>(
        (const float*)p_kvd + (long)C_ * HW_, (long)C2_ * HW_, HW_,
        (const uint32_t*)p_mwh, (const uint32_t*)p_mwl, (long)C_ * 96, 96, 6,
        out, (long)C_ * HW_, HW_);
}

// round 14
// speedup vs baseline: 1.0602x; 1.0602x over previous
#include <cuda_runtime.h>
#include <cuda_bf16.h>
#include <cstdint>
#include <math.h>

#define B_    8
#define C_    192
#define C2_   384
#define HH_   128
#define WW_   128
#define HW_   16384
#define HEADS_ 4
#define CH_   48
#define NSLICE 8
#define TAPS  36
#define TPI   1024

// ---------------- scratch (device globals) ------------------------------------
__device__ float g_kv0[B_*C2_*HW_];
__device__ float g_kvd[B_*C2_*HW_];       // k rows 0..191, v rows 192..383
__device__ float g_q  [B_*C_*HW_];
__device__ float g_part[NSLICE*B_*HEADS_*CH_*CH_];
__device__ float g_attn[B_*HEADS_*CH_*CH_];
__device__ float g_nsq[2*NSLICE*B_*C_];
__device__ uint32_t g_kvwH[C2_*96],   g_kvwL[C2_*96];
__device__ uint32_t g_mwH[B_*C_*96],  g_mwL[B_*C_*96];
__device__ float    g_wq9[C_*C_*9];
__device__ uint32_t g_uwH[TAPS*C_*96], g_uwL[TAPS*C_*96];
__device__ float    g_vw[(long)B_*TAPS*C_*TPI];
__device__ float    g_wm[(long)B_*TAPS*C_*TPI];

// ---------------- helpers ------------------------------------------------------
__device__ __forceinline__ uint32_t s2u(const void* p){
    uint32_t a;
    asm("{ .reg .u64 t; cvta.to.shared.u64 t, %1; cvt.u32.u64 %0, t; }" : "=r"(a) : "l"(p));
    return a;
}
__device__ __forceinline__ void split2(float v0, float v1, uint32_t& hp, uint32_t& lp){
    __nv_bfloat16 h0 = __float2bfloat16_rn(v0);
    __nv_bfloat16 h1 = __float2bfloat16_rn(v1);
    __nv_bfloat16 l0 = __float2bfloat16_rn(v0 - __bfloat162float(h0));
    __nv_bfloat16 l1 = __float2bfloat16_rn(v1 - __bfloat162float(h1));
    hp = (uint32_t)__bfloat16_as_ushort(h0) | ((uint32_t)__bfloat16_as_ushort(h1) << 16);
    lp = (uint32_t)__bfloat16_as_ushort(l0) | ((uint32_t)__bfloat16_as_ushort(l1) << 16);
}
__device__ __forceinline__ void ldsm4(uint32_t& r0, uint32_t& r1, uint32_t& r2,
                                      uint32_t& r3, uint32_t addr){
    asm volatile("ldmatrix.sync.aligned.m8n8.x4.shared.b16 {%0,%1,%2,%3}, [%4];"
                 : "=r"(r0), "=r"(r1), "=r"(r2), "=r"(r3) : "r"(addr));
}

// ---------------- weight preps -------------------------------------------------
__global__ void prep_kvw_kernel(const float* __restrict__ kv_w){
    int idx = blockIdx.x * 256 + threadIdx.x;
    int oc = idx / 96, c = idx % 96;
    uint32_t hp, lp;
    split2(kv_w[oc*C_ + 2*c], kv_w[oc*C_ + 2*c + 1], hp, lp);
    g_kvwH[idx] = hp; g_kvwL[idx] = lp;
}
__global__ void __launch_bounds__(192) prep_qw_kernel(
        const float* __restrict__ q_dw_w, const float* __restrict__ q_w){
    __shared__ float buf[3 * C_];
    const int o = blockIdx.x, ty = blockIdx.y, tid = threadIdx.x;
    #pragma unroll
    for (int j = 0; j < 3; j++)
        buf[tid * 3 + j] = q_dw_w[(o * C_ + tid) * 9 + ty * 3 + j];
    __syncthreads();
    float s[3] = {};
    const int i = tid;
    for (int m = 0; m < C_; m++){
        float qv = q_w[m * C_ + i];
        #pragma unroll
        for (int j = 0; j < 3; j++) s[j] = fmaf(buf[m * 3 + j], qv, s[j]);
    }
    #pragma unroll
    for (int j = 0; j < 3; j++)
        g_wq9[((long)o * 9 + ty * 3 + j) * C_ + i] = s[j];
}
__global__ void prep_mw_kernel(const float* __restrict__ projw){
    int idx = blockIdx.x * 256 + threadIdx.x;
    int c = idx % 96;
    int o = (idx / 96) % C_;
    int b = idx / (96 * C_);
    float sv[2];
    #pragma unroll
    for (int j = 0; j < 2; j++){
        int k = 2*c + j;
        int h = k / CH_, dl = k % CH_;
        const float* aw = &g_attn[((b * HEADS_ + h) * CH_) * CH_ + dl];
        const float* pw = &projw[o * C_ + h * CH_];
        float s = 0.f;
        for (int cc = 0; cc < CH_; cc++) s = fmaf(pw[cc], aw[cc * CH_], s);
        sv[j] = s;
    }
    uint32_t hp, lp;
    split2(sv[0], sv[1], hp, lp);
    g_mwH[idx] = hp; g_mwL[idx] = lp;
}

// ---------------- winograd weight transform: U = G W G^T -----------------------
__global__ void __launch_bounds__(96) wino_wt_kernel(){
    const int o = blockIdx.x, j = threadIdx.x;
    float Ua[36], Ub[36];
    #pragma unroll
    for (int half = 0; half < 2; half++){
        float* U = half ? Ub : Ua;
        int i = 2*j + half;
        float w[3][3];
        #pragma unroll
        for (int r = 0; r < 3; r++)
            #pragma unroll
            for (int c = 0; c < 3; c++)
                w[r][c] = g_wq9[((long)o*9 + r*3 + c)*C_ + i];
        float gw[6][3];
        #pragma unroll
        for (int c = 0; c < 3; c++){
            gw[0][c] = 0.25f*w[0][c];
            gw[1][c] = (-w[0][c]-w[1][c]-w[2][c])*(1.f/6.f);
            gw[2][c] = (-w[0][c]+w[1][c]-w[2][c])*(1.f/6.f);
            gw[3][c] = w[0][c]*(1.f/24.f) + w[1][c]*(1.f/12.f) + w[2][c]*(1.f/6.f);
            gw[4][c] = w[0][c]*(1.f/24.f) - w[1][c]*(1.f/12.f) + w[2][c]*(1.f/6.f);
            gw[5][c] = w[2][c];
        }
        #pragma unroll
        for (int r = 0; r < 6; r++){
            U[r*6+0] = 0.25f*gw[r][0];
            U[r*6+1] = (-gw[r][0]-gw[r][1]-gw[r][2])*(1.f/6.f);
            U[r*6+2] = (-gw[r][0]+gw[r][1]-gw[r][2])*(1.f/6.f);
            U[r*6+3] = gw[r][0]*(1.f/24.f) + gw[r][1]*(1.f/12.f) + gw[r][2]*(1.f/6.f);
            U[r*6+4] = gw[r][0]*(1.f/24.f) - gw[r][1]*(1.f/12.f) + gw[r][2]*(1.f/6.f);
            U[r*6+5] = gw[r][2];
        }
    }
    #pragma unroll
    for (int tp = 0; tp < 36; tp++){
        uint32_t hp, lp;
        split2(Ua[tp], Ub[tp], hp, lp);
        g_uwH[(long)tp*C_*96 + o*96 + j] = hp;
        g_uwL[(long)tp*C_*96 + o*96 + j] = lp;
    }
}

// ---------------- winograd input transform (ALU-lean, coalesced) ----------------
__global__ void __launch_bounds__(256) wino_in_kernel(const float* __restrict__ y){
    __shared__ float inS[8][6][132];
    const int TY  = blockIdx.x;
    const int ic0 = blockIdx.y * 8;
    const int b   = blockIdx.z;
    const int tid = threadIdx.x;
    const int wrp = tid >> 5, lane = tid & 31;
    {
        const int gy0 = 4*TY - 1;
        #pragma unroll
        for (int rr = 0; rr < 6; rr++){
            int rowid = wrp + rr * 8;
            int ic = rowid / 6, r = rowid % 6;
            int gy = gy0 + r;
            const float* src = y + ((long)(b*C_ + ic0 + ic))*HW_ + gy*WW_;
            bool rowok = (unsigned)gy < 128u;
            float* dst = &inS[ic][r][0];
            #pragma unroll
            for (int j = 0; j < 5; j++){
                int col = lane + j*32 - 1;
                if (j < 4 || col < 131){
                    float v = 0.f;
                    if (rowok && (unsigned)col < 128u) v = src[col];
                    if (col + 1 < 132) dst[col + 1] = v;
                }
            }
        }
    }
    __syncthreads();
    const int tx  = lane;
    const int icl = wrp;
    float vv[36];
    {
        float d[6][6];
        #pragma unroll
        for (int r = 0; r < 6; r++)
            #pragma unroll
            for (int c = 0; c < 6; c++)
                d[r][c] = inS[icl][r][4*tx + c];
        float t[6][6];
        #pragma unroll
        for (int c = 0; c < 6; c++){
            t[0][c] =  4.f*d[0][c] - 5.f*d[2][c] + d[4][c];
            t[1][c] = -4.f*d[1][c] - 4.f*d[2][c] + d[3][c] + d[4][c];
            t[2][c] =  4.f*d[1][c] - 4.f*d[2][c] - d[3][c] + d[4][c];
            t[3][c] = -2.f*d[1][c] - d[2][c] + 2.f*d[3][c] + d[4][c];
            t[4][c] =  2.f*d[1][c] - d[2][c] - 2.f*d[3][c] + d[4][c];
            t[5][c] =  4.f*d[1][c] - 5.f*d[3][c] + d[5][c];
        }
        #pragma unroll
        for (int r = 0; r < 6; r++){
            vv[r*6+0] =  4.f*t[r][0] - 5.f*t[r][2] + t[r][4];
            vv[r*6+1] = -4.f*t[r][1] - 4.f*t[r][2] + t[r][3] + t[r][4];
            vv[r*6+2] =  4.f*t[r][1] - 4.f*t[r][2] - t[r][3] + t[r][4];
            vv[r*6+3] = -2.f*t[r][1] - t[r][2] + 2.f*t[r][3] + t[r][4];
            vv[r*6+4] =  2.f*t[r][1] - t[r][2] - 2.f*t[r][3] + t[r][4];
            vv[r*6+5] =  4.f*t[r][1] - 5.f*t[r][3] + t[r][5];
        }
    }
    float* p = g_vw + (((long)(b*TAPS))*C_ + (ic0 + icl))*TPI + TY*32 + tx;
    #pragma unroll
    for (int tp = 0; tp < 36; tp++){
        *p = vv[tp];
        p += (long)C_ * TPI;
    }
}

// ---------------- winograd output transform ------------------------------------
__global__ void __launch_bounds__(128) wino_out_kernel(){
    const int tb = blockIdx.x, oc = blockIdx.y, b = blockIdx.z;
    const int tile = tb*128 + threadIdx.x;
    float m[36];
    const float* p = g_wm + (((long)(b*TAPS))*C_ + oc)*TPI + tile;
    #pragma unroll
    for (int tp = 0; tp < 36; tp++){
        m[tp] = *p;
        p += (long)C_ * TPI;
    }
    float t[4][6];
    #pragma unroll
    for (int c = 0; c < 6; c++){
        float m0=m[c], m1=m[6+c], m2=m[12+c], m3=m[18+c], m4=m[24+c], m5=m[30+c];
        t[0][c] = m0+m1+m2+m3+m4;
        t[1][c] = m1-m2+2.f*m3-2.f*m4;
        t[2][c] = m1+m2+4.f*m3+4.f*m4;
        t[3][c] = m1-m2+8.f*m3-8.f*m4+m5;
    }
    int ty = tile >> 5, tx = tile & 31;
    float* op = &g_q[((long)(b*C_ + oc))*HW_ + (4*ty)*WW_ + 4*tx];
    #pragma unroll
    for (int r = 0; r < 4; r++){
        float o0 = t[r][0]+t[r][1]+t[r][2]+t[r][3]+t[r][4];
        float o1 = t[r][1]-t[r][2]+2.f*t[r][3]-2.f*t[r][4];
        float o2 = t[r][1]+t[r][2]+4.f*t[r][3]+4.f*t[r][4];
        float o3 = t[r][1]-t[r][2]+8.f*t[r][3]-8.f*t[r][4]+t[r][5];
        *(float4*)&op[r*WW_] = make_float4(o0,o1,o2,o3);
    }
}

// ---------------- 3-term bf16 mma.sync GEMM, M128 x N96, 256 thr, 2 CTA/SM -----
#define ROWB 80
#define KPW  20
#define AHB  (128 * ROWB)          // 10240
#define BHB  (96 * ROWB)           // 7680
#define STG  (2*AHB + 2*BHB)       // 35840
#define TG_SMEM (3*STG)            // 107520

template<int MODE>
__global__ void __launch_bounds__(256, 2) mma_gemm_kernel(
    const float* __restrict__ A, long aBS, int aRow,
    const uint32_t* __restrict__ BH, const uint32_t* __restrict__ BL, long bBS,
    int bRow, int NG, float* __restrict__ Out, long oBS, int oRow)
{
    extern __shared__ char smem[];
    const uint32_t sb = s2u(smem);
    const int tid = threadIdx.x;
    const int b = blockIdx.z;
    const int pBase = blockIdx.x * 128;
    const int nBase = blockIdx.y * 96;
    const float* Ab = A + (long)b * aBS;
    const long bsel2 = (MODE == 2) ? (long)(b % TAPS) : (long)b;
    const uint32_t* BHb = BH + bsel2 * bBS + (long)nBase * bRow;
    const uint32_t* BLb = BL + bsel2 * bBS + (long)nBase * bRow;

    const int lane = tid & 31, wid = tid >> 5;
    const int wm = (wid & 3) * 32;        // 4 warps along M (128)
    const int wn = (wid >> 2) * 48;       // 2 warps along N (96)
    const int g8 = lane >> 2, tig = lane & 3;
    const uint32_t arow = (lane & 7) + ((lane >> 3) & 1) * 8;
    const uint32_t acol = ((lane >> 4) & 1) * 4;
    const uint32_t brow = (lane & 7) + ((lane >> 4) & 1) * 8;
    const uint32_t bcol = ((lane >> 3) & 1) * 4;
    const int am = tid & 127, akp = (tid >> 7) * 8;   // A: row, starting k-pair

    float acc[2][6][4];
    #pragma unroll
    for (int a = 0; a < 2; a++)
        #pragma unroll
        for (int n = 0; n < 6; n++)
            #pragma unroll
            for (int c = 0; c < 4; c++) acc[a][n][c] = 0.f;

    float rbuf[2][16];
    auto ldA = [&](int g, float* rb){
        const float* base = Ab + pBase + am + (long)(g*32 + 2*akp) * aRow;
        #pragma unroll
        for (int j = 0; j < 8; j++){
            rb[2*j]   = __ldg(base);
            rb[2*j+1] = __ldg(base + aRow);
            base += 2L * aRow;
        }
    };
    auto stA = [&](int sel, const float* rb){
        uint32_t abuf = sb + (uint32_t)sel*STG + am*ROWB + akp*4;
        #pragma unroll
        for (int j = 0; j < 8; j++){
            uint32_t hp, lp; split2(rb[2*j], rb[2*j+1], hp, lp);
            asm volatile("st.shared.b32 [%0], %1;" :: "r"(abuf + j*4), "r"(hp));
            asm volatile("st.shared.b32 [%0], %1;" :: "r"(abuf + AHB + j*4), "r"(lp));
        }
    };
    auto stageB = [&](int g, int sel){
        const uint32_t bhbuf = sb + sel * STG + 2 * AHB;
        const uint32_t blbuf = bhbuf + BHB;
        #pragma unroll
        for (int i = 0; i < 3; i++){
            int idx = tid + i * 256;            // 768 = 96 n x 4 c16 x 2 arr
            int n = idx >> 3, r = idx & 7;
            int arr = r >> 2, c16 = r & 3;
            uint32_t sa = (arr ? blbuf : bhbuf) + n * ROWB + c16 * 16;
            const uint32_t* gp = (arr ? BLb : BHb) + (long)n * bRow + g * 16 + c16 * 4;
            asm volatile("cp.async.cg.shared.global [%0], [%1], 16;" :: "r"(sa), "l"(gp) : "memory");
        }
        asm volatile("cp.async.commit_group;" ::: "memory");
    };

    ldA(0, rbuf[0]);
    stageB(0, 0);
    ldA(1, rbuf[1]);
    stageB(1, 1);
    stA(0, rbuf[0]);
    for (int g = 0; g < NG; g++){
        const int sel = g % 3;
        if (g + 1 < NG) stA((g + 1) % 3, rbuf[(g + 1) % 2]);
        if (g + 2 < NG){
            ldA(g + 2, rbuf[(g + 2) % 2]);
            stageB(g + 2, (g + 2) % 3);
            asm volatile("cp.async.wait_group 2;" ::: "memory");
        } else if (g + 1 < NG){
            asm volatile("cp.async.wait_group 1;" ::: "memory");
        } else {
            asm volatile("cp.async.wait_group 0;" ::: "memory");
        }
        __syncthreads();
        const uint32_t abase  = sb + sel * STG;
        const uint32_t albase = abase + AHB;
        const uint32_t bhbase = abase + 2 * AHB;
        const uint32_t blbase = bhbase + BHB;
        #pragma unroll
        for (int ks = 0; ks < 2; ks++){
            uint32_t bh[6][2], bl[6][2];
            #pragma unroll
            for (int j = 0; j < 3; j++){
                uint32_t off = (uint32_t)((wn + j * 16 + brow) * ROWB + (ks * 8 + bcol) * 4);
                ldsm4(bh[2*j][0], bh[2*j][1], bh[2*j+1][0], bh[2*j+1][1], bhbase + off);
                ldsm4(bl[2*j][0], bl[2*j][1], bl[2*j+1][0], bl[2*j+1][1], blbase + off);
            }
            #pragma unroll
            for (int mt = 0; mt < 2; mt++){
                uint32_t off = (uint32_t)((wm + mt * 16 + arow) * ROWB + (ks * 8 + acol) * 4);
                uint32_t ah0, ah1, ah2, ah3, al0, al1, al2, al3;
                ldsm4(ah0, ah1, ah2, ah3, abase + off);
                ldsm4(al0, al1, al2, al3, albase + off);
                #pragma unroll
                for (int nt = 0; nt < 6; nt++){
                    asm volatile(
                        "mma.sync.aligned.m16n8k16.row.col.f32.bf16.bf16.f32 "
                        "{%0,%1,%2,%3}, {%4,%5,%6,%7}, {%8,%9}, {%0,%1,%2,%3};"
                        : "+f"(acc[mt][nt][0]), "+f"(acc[mt][nt][1]),
                          "+f"(acc[mt][nt][2]), "+f"(acc[mt][nt][3])
                        : "r"(ah0), "r"(ah1), "r"(ah2), "r"(ah3),
                          "r"(bh[nt][0]), "r"(bh[nt][1]));
                    asm volatile(
                        "mma.sync.aligned.m16n8k16.row.col.f32.bf16.bf16.f32 "
                        "{%0,%1,%2,%3}, {%4,%5,%6,%7}, {%8,%9}, {%0,%1,%2,%3};"
                        : "+f"(acc[mt][nt][0]), "+f"(acc[mt][nt][1]),
                          "+f"(acc[mt][nt][2]), "+f"(acc[mt][nt][3])
                        : "r"(ah0), "r"(ah1), "r"(ah2), "r"(ah3),
                          "r"(bl[nt][0]), "r"(bl[nt][1]));
                    asm volatile(
                        "mma.sync.aligned.m16n8k16.row.col.f32.bf16.bf16.f32 "
                        "{%0,%1,%2,%3}, {%4,%5,%6,%7}, {%8,%9}, {%0,%1,%2,%3};"
                        : "+f"(acc[mt][nt][0]), "+f"(acc[mt][nt][1]),
                          "+f"(acc[mt][nt][2]), "+f"(acc[mt][nt][3])
                        : "r"(al0), "r"(al1), "r"(al2), "r"(al3),
                          "r"(bh[nt][0]), "r"(bh[nt][1]));
                }
            }
        }
        __syncthreads();
    }

    float* Cs = (float*)smem;
    #pragma unroll
    for (int mt = 0; mt < 2; mt++)
        #pragma unroll
        for (int nt = 0; nt < 6; nt++){
            int m0 = wm + mt * 16 + g8;
            int n0 = wn + nt * 8 + tig * 2;
            Cs[n0 * 132 + m0]           = acc[mt][nt][0];
            Cs[(n0 + 1) * 132 + m0]     = acc[mt][nt][1];
            Cs[n0 * 132 + m0 + 8]       = acc[mt][nt][2];
            Cs[(n0 + 1) * 132 + m0 + 8] = acc[mt][nt][3];
        }
    __syncthreads();
    float* Ob = Out + (long)b * oBS;
    #pragma unroll
    for (int i = 0; i < 12; i++){
        int idx = tid + i * 256;
        int n = idx >> 5, c4 = idx & 31;
        *(float4*)&Ob[(long)(nBase + n) * oRow + pBase + c4 * 4] =
            *(float4*)&Cs[n * 132 + c4 * 4];
    }
}

// ---------------- depthwise 3x3, smem-tiled ------------------------------------
__global__ void __launch_bounds__(256) dw_kernel(const float* __restrict__ dww) {
    __shared__ float tile[34][128];
    __shared__ float ws[9];
    const int b = blockIdx.z, c = blockIdx.y, rb = blockIdx.x * 32;
    const int tid = threadIdx.x;
    if (tid < 9) ws[tid] = dww[c * 9 + tid];
    const float* ip = &g_kv0[((long)(b * C2_ + c)) * HW_];
    for (int idx = tid; idx < 34 * 128; idx += 256){
        int lr = idx >> 7, col = idx & 127;
        int gy = rb - 1 + lr;
        tile[lr][col] = ((unsigned)gy < 128u) ? ip[gy * 128 + col] : 0.f;
    }
    __syncthreads();
    const int lrow = tid >> 3, c0 = (tid & 7) * 16;
    float wv[3][18];
    #pragma unroll
    for (int dy = 0; dy < 3; dy++){
        const float* tr = tile[lrow + dy];
        wv[dy][0]  = (c0 > 0) ? tr[c0 - 1] : 0.f;
        #pragma unroll
        for (int q = 0; q < 4; q++){
            float4 v = *(const float4*)&tr[c0 + q * 4];
            wv[dy][1 + q*4] = v.x; wv[dy][2 + q*4] = v.y;
            wv[dy][3 + q*4] = v.z; wv[dy][4 + q*4] = v.w;
        }
        wv[dy][17] = (c0 + 16 < 128) ? tr[c0 + 16] : 0.f;
    }
    float o[16];
    #pragma unroll
    for (int cc = 0; cc < 16; cc++){
        float a = 0.f;
        #pragma unroll
        for (int dy = 0; dy < 3; dy++)
            #pragma unroll
            for (int dx = 0; dx < 3; dx++)
                a = fmaf(ws[dy * 3 + dx], wv[dy][cc + dx], a);
        o[cc] = a;
    }
    float* op = &g_kvd[((long)(b * C2_ + c)) * HW_ + (rb + lrow) * 128 + c0];
    #pragma unroll
    for (int q = 0; q < 4; q++)
        *(float4*)&op[q * 4] = make_float4(o[q*4], o[q*4+1], o[q*4+2], o[q*4+3]);
}

// ---------------- QK^T partial dots + fused sumsq partials ---------------------
__global__ __launch_bounds__(256) void attn_dot_kernel() {
    __shared__ float qS[CH_ * 68];
    __shared__ float kS[CH_ * 68];
    __shared__ float redq[8][12], redk[8][12];
    const int sl = blockIdx.x, h = blockIdx.y, b = blockIdx.z;
    const int tid = threadIdx.x;
    const int c0 = (tid >> 4) * 3, d0 = (tid & 15) * 3;
    float acc[3][3] = {};
    float sqq[12] = {}, sqk[12] = {};
    const float* qbase = &g_q[((long)(b * C_) + h * CH_) * HW_];
    const float* kbase = &g_kvd[((long)(b * C2_) + h * CH_) * HW_];
    const int n0 = sl * (HW_ / NSLICE);
    for (int chn = 0; chn < HW_ / NSLICE; chn += 64) {
        #pragma unroll
        for (int i = 0; i < 12; i++){
            int idx = tid + i * 256;
            int r = idx >> 6, col = idx & 63;
            float vq = qbase[(long)r * HW_ + n0 + chn + col];
            float vk = kbase[(long)r * HW_ + n0 + chn + col];
            qS[r * 68 + col] = vq; kS[r * 68 + col] = vk;
            sqq[i] = fmaf(vq, vq, sqq[i]);
            sqk[i] = fmaf(vk, vk, sqk[i]);
        }
        __syncthreads();
        #pragma unroll
        for (int n = 0; n < 64; n += 4) {
            float4 qv[3], kv[3];
            #pragma unroll
            for (int i = 0; i < 3; i++) qv[i] = *(const float4*)&qS[(c0 + i) * 68 + n];
            #pragma unroll
            for (int i = 0; i < 3; i++) kv[i] = *(const float4*)&kS[(d0 + i) * 68 + n];
            #pragma unroll
            for (int i = 0; i < 3; i++)
                #pragma unroll
                for (int j = 0; j < 3; j++) {
                    acc[i][j] = fmaf(qv[i].x, kv[j].x, acc[i][j]);
                    acc[i][j] = fmaf(qv[i].y, kv[j].y, acc[i][j]);
                    acc[i][j] = fmaf(qv[i].z, kv[j].z, acc[i][j]);
                    acc[i][j] = fmaf(qv[i].w, kv[j].w, acc[i][j]);
                }
        }
        __syncthreads();
    }
    const int w = tid >> 5;
    #pragma unroll
    for (int i = 0; i < 12; i++){
        float vq = sqq[i], vk = sqk[i];
        #pragma unroll
        for (int off = 16; off; off >>= 1){
            vq += __shfl_xor_sync(0xffffffffu, vq, off);
            vk += __shfl_xor_sync(0xffffffffu, vk, off);
        }
        if ((tid & 31) == 0){ redq[w][i] = vq; redk[w][i] = vk; }
    }
    __syncthreads();
    if (tid < CH_){
        int r0 = tid & 3, ii = tid >> 2;
        float sq = redq[2*r0][ii] + redq[2*r0+1][ii];
        float sk = redk[2*r0][ii] + redk[2*r0+1][ii];
        g_nsq[((long)sl * B_ + b) * C_ + h * CH_ + tid] = sq;
        g_nsq[(long)NSLICE * B_ * C_ + ((long)sl * B_ + b) * C_ + h * CH_ + tid] = sk;
    }
    float* outp = &g_part[(((long)sl * B_ + b) * HEADS_ + h) * CH_ * CH_];
    #pragma unroll
    for (int i = 0; i < 3; i++)
        #pragma unroll
        for (int j = 0; j < 3; j++)
            outp[(c0 + i) * CH_ + d0 + j] = acc[i][j];
}

// ---------------- scale + softmax ---------------------------------------------
__global__ void softmax_kernel(const float* __restrict__ temp) {
    __shared__ float ikS[CH_];
    const int h = blockIdx.x & 3, b = blockIdx.x >> 2;
    const int c = threadIdx.x;
    if (c < CH_){
        float s = 0.f;
        for (int sl = 0; sl < NSLICE; sl++)
            s += g_nsq[(long)NSLICE * B_ * C_ + ((long)sl * B_ + b) * C_ + h * CH_ + c];
        ikS[c] = 1.0f / fmaxf(sqrtf(s), 1e-12f);
    }
    __syncthreads();
    if (c >= CH_) return;
    float sq = 0.f;
    for (int sl = 0; sl < NSLICE; sl++)
        sq += g_nsq[((long)sl * B_ + b) * C_ + h * CH_ + c];
    const float iq = 1.0f / fmaxf(sqrtf(sq), 1e-12f);
    const float t = temp[h] * logf((float)CH_);
    float row[CH_];
    float m = -1e30f;
    for (int d = 0; d < CH_; d++) {
        float s = 0.f;
        for (int sl = 0; sl < NSLICE; sl++)
            s += g_part[(((long)sl * B_ + b) * HEADS_ + h) * CH_ * CH_ + c * CH_ + d];
        row[d] = s * iq * ikS[d] * t;
        m = fmaxf(m, row[d]);
    }
    float sum = 0.f;
    for (int d = 0; d < CH_; d++) {
        row[d] = expf(row[d] - m);
        sum += row[d];
    }
    float inv = 1.0f / sum;
    for (int d = 0; d < CH_; d++)
        g_attn[((b * HEADS_ + h) * CH_ + c) * CH_ + d] = row[d] * inv;
}

// ---------------- launch ------------------------------------------------------
extern "C" void kernel_launch(void* const* d_in, const int* in_sizes, int n_in,
                              void* d_out, int out_size) {
    const float* x       = (const float*)d_in[0];
    const float* y       = (const float*)d_in[1];
    const float* kv_w    = (const float*)d_in[2];
    const float* kv_dw_w = (const float*)d_in[3];
    const float* q_w     = (const float*)d_in[4];
    const float* q_dw_w  = (const float*)d_in[5];
    const float* proj_w  = (const float*)d_in[6];
    const float* temp    = (const float*)d_in[7];
    float* out = (float*)d_out;

    void *p_kv0, *p_kvd, *p_q, *p_kwh, *p_kwl, *p_mwh, *p_mwl;
    void *p_uwh, *p_uwl, *p_vw, *p_wm;
    cudaGetSymbolAddress(&p_kv0, g_kv0);
    cudaGetSymbolAddress(&p_kvd, g_kvd);
    cudaGetSymbolAddress(&p_q,   g_q);
    cudaGetSymbolAddress(&p_kwh, g_kvwH); cudaGetSymbolAddress(&p_kwl, g_kvwL);
    cudaGetSymbolAddress(&p_mwh, g_mwH);  cudaGetSymbolAddress(&p_mwl, g_mwL);
    cudaGetSymbolAddress(&p_uwh, g_uwH);  cudaGetSymbolAddress(&p_uwl, g_uwL);
    cudaGetSymbolAddress(&p_vw,  g_vw);   cudaGetSymbolAddress(&p_wm,  g_wm);

    cudaFuncSetAttribute(mma_gemm_kernel<0>, cudaFuncAttributeMaxDynamicSharedMemorySize, TG_SMEM);
    cudaFuncSetAttribute(mma_gemm_kernel<2>, cudaFuncAttributeMaxDynamicSharedMemorySize, TG_SMEM);

    prep_qw_kernel<<<dim3(C_, 3), 192>>>(q_dw_w, q_w);                                 // #1
    wino_wt_kernel<<<C_, 96>>>();                                                      // #2
    wino_in_kernel<<<dim3(32, 24, B_), 256>>>(y);                                      // #3

    // winograd batched per-tap GEMM (N=96 x2)                    — launch #4 (ncu slot)
    mma_gemm_kernel<2><<<dim3(TPI / 128, 2, B_ * TAPS), 256, TG_SMEM>>>(
        (const float*)p_vw, (long)C_ * TPI, TPI,
        (const uint32_t*)p_uwh, (const uint32_t*)p_uwl, (long)C_ * 96, 96, 6,
        (float*)p_wm, (long)C_ * TPI, TPI);

    prep_kvw_kernel<<<(C2_ * 96) / 256, 256>>>(kv_w);                                  // #5

    // kv 1x1: N=384 as 4 chunks of 96                                                 // #6
    mma_gemm_kernel<0><<<dim3(HW_ / 128, 4, B_), 256, TG_SMEM>>>(
        x, (long)C_ * HW_, HW_,
        (const uint32_t*)p_kwh, (const uint32_t*)p_kwl, 0L, 96, 6,
        (float*)p_kv0, (long)C2_ * HW_, HW_);

    dw_kernel<<<dim3(HH_ / 32, C2_, B_), 256>>>(kv_dw_w);                              // #7
    wino_out_kernel<<<dim3(TPI / 128, C_, B_), 128>>>();                               // #8

    attn_dot_kernel<<<dim3(NSLICE, HEADS_, B_), 256>>>();                              // #9
    softmax_kernel<<<B_ * HEADS_, 64>>>(temp);                                         // #10
    prep_mw_kernel<<<(B_ * C_ * 96) / 256, 256>>>(proj_w);                             // #11

    // fused (proj @ attn) @ v -> out : N=192 as 2 chunks of 96                        // #12
    mma_gemm_kernel<0><<<dim3(HW_ / 128, 2, B_), 256, TG_SMEM>>>(
        (const float*)p_kvd + (long)C_ * HW_, (long)C2_ * HW_, HW_,
        (const uint32_t*)p_mwh, (const uint32_t*)p_mwl, (long)C_ * 96, 96, 6,
        out, (long)C_ * HW_, HW_);
}

// round 15
// speedup vs baseline: 1.0946x; 1.0324x over previous
#include <cuda_runtime.h>
#include <cuda_bf16.h>
#include <cstdint>
#include <math.h>

#define B_    8
#define C_    192
#define C2_   384
#define HH_   128
#define WW_   128
#define HW_   16384
#define HEADS_ 4
#define CH_   48
#define NSLICE 8
#define TAPS  36
#define TPI   1024

// ---------------- scratch (device globals) ------------------------------------
__device__ float g_kv0[B_*C2_*HW_];
__device__ float g_kvd[B_*C2_*HW_];       // k rows 0..191, v rows 192..383
__device__ float g_q  [B_*C_*HW_];
__device__ float g_part[NSLICE*B_*HEADS_*CH_*CH_];
__device__ float g_attn[B_*HEADS_*CH_*CH_];
__device__ float g_nsq[2*NSLICE*B_*C_];
__device__ uint32_t g_kvwH[C2_*96],   g_kvwL[C2_*96];
__device__ uint32_t g_mwH[B_*C_*96],  g_mwL[B_*C_*96];
__device__ float    g_wq9[C_*C_*9];
__device__ uint32_t g_uwH[TAPS*C_*96], g_uwL[TAPS*C_*96];
__device__ float    g_vw[(long)B_*TAPS*C_*TPI];
__device__ float    g_wm[(long)B_*TAPS*C_*TPI];

// ---------------- helpers ------------------------------------------------------
__device__ __forceinline__ uint32_t s2u(const void* p){
    uint32_t a;
    asm("{ .reg .u64 t; cvta.to.shared.u64 t, %1; cvt.u32.u64 %0, t; }" : "=r"(a) : "l"(p));
    return a;
}
__device__ __forceinline__ void split2(float v0, float v1, uint32_t& hp, uint32_t& lp){
    __nv_bfloat16 h0 = __float2bfloat16_rn(v0);
    __nv_bfloat16 h1 = __float2bfloat16_rn(v1);
    __nv_bfloat16 l0 = __float2bfloat16_rn(v0 - __bfloat162float(h0));
    __nv_bfloat16 l1 = __float2bfloat16_rn(v1 - __bfloat162float(h1));
    hp = (uint32_t)__bfloat16_as_ushort(h0) | ((uint32_t)__bfloat16_as_ushort(h1) << 16);
    lp = (uint32_t)__bfloat16_as_ushort(l0) | ((uint32_t)__bfloat16_as_ushort(l1) << 16);
}
__device__ __forceinline__ void ldsm4(uint32_t& r0, uint32_t& r1, uint32_t& r2,
                                      uint32_t& r3, uint32_t addr){
    asm volatile("ldmatrix.sync.aligned.m8n8.x4.shared.b16 {%0,%1,%2,%3}, [%4];"
                 : "=r"(r0), "=r"(r1), "=r"(r2), "=r"(r3) : "r"(addr));
}

// ---------------- weight preps -------------------------------------------------
__global__ void prep_kvw_kernel(const float* __restrict__ kv_w){
    int idx = blockIdx.x * 256 + threadIdx.x;
    int oc = idx / 96, c = idx % 96;
    uint32_t hp, lp;
    split2(kv_w[oc*C_ + 2*c], kv_w[oc*C_ + 2*c + 1], hp, lp);
    g_kvwH[idx] = hp; g_kvwL[idx] = lp;
}
__global__ void __launch_bounds__(192) prep_qw_kernel(
        const float* __restrict__ q_dw_w, const float* __restrict__ q_w){
    __shared__ float buf[3 * C_];
    const int o = blockIdx.x, ty = blockIdx.y, tid = threadIdx.x;
    #pragma unroll
    for (int j = 0; j < 3; j++)
        buf[tid * 3 + j] = q_dw_w[(o * C_ + tid) * 9 + ty * 3 + j];
    __syncthreads();
    float s[3] = {};
    const int i = tid;
    for (int m = 0; m < C_; m++){
        float qv = q_w[m * C_ + i];
        #pragma unroll
        for (int j = 0; j < 3; j++) s[j] = fmaf(buf[m * 3 + j], qv, s[j]);
    }
    #pragma unroll
    for (int j = 0; j < 3; j++)
        g_wq9[((long)o * 9 + ty * 3 + j) * C_ + i] = s[j];
}
__global__ void prep_mw_kernel(const float* __restrict__ projw){
    int idx = blockIdx.x * 256 + threadIdx.x;
    int c = idx % 96;
    int o = (idx / 96) % C_;
    int b = idx / (96 * C_);
    float sv[2];
    #pragma unroll
    for (int j = 0; j < 2; j++){
        int k = 2*c + j;
        int h = k / CH_, dl = k % CH_;
        const float* aw = &g_attn[((b * HEADS_ + h) * CH_) * CH_ + dl];
        const float* pw = &projw[o * C_ + h * CH_];
        float s = 0.f;
        for (int cc = 0; cc < CH_; cc++) s = fmaf(pw[cc], aw[cc * CH_], s);
        sv[j] = s;
    }
    uint32_t hp, lp;
    split2(sv[0], sv[1], hp, lp);
    g_mwH[idx] = hp; g_mwL[idx] = lp;
}

// ---------------- winograd weight transform: U = G W G^T -----------------------
__global__ void __launch_bounds__(96) wino_wt_kernel(){
    const int o = blockIdx.x, j = threadIdx.x;
    float Ua[36], Ub[36];
    #pragma unroll
    for (int half = 0; half < 2; half++){
        float* U = half ? Ub : Ua;
        int i = 2*j + half;
        float w[3][3];
        #pragma unroll
        for (int r = 0; r < 3; r++)
            #pragma unroll
            for (int c = 0; c < 3; c++)
                w[r][c] = g_wq9[((long)o*9 + r*3 + c)*C_ + i];
        float gw[6][3];
        #pragma unroll
        for (int c = 0; c < 3; c++){
            gw[0][c] = 0.25f*w[0][c];
            gw[1][c] = (-w[0][c]-w[1][c]-w[2][c])*(1.f/6.f);
            gw[2][c] = (-w[0][c]+w[1][c]-w[2][c])*(1.f/6.f);
            gw[3][c] = w[0][c]*(1.f/24.f) + w[1][c]*(1.f/12.f) + w[2][c]*(1.f/6.f);
            gw[4][c] = w[0][c]*(1.f/24.f) - w[1][c]*(1.f/12.f) + w[2][c]*(1.f/6.f);
            gw[5][c] = w[2][c];
        }
        #pragma unroll
        for (int r = 0; r < 6; r++){
            U[r*6+0] = 0.25f*gw[r][0];
            U[r*6+1] = (-gw[r][0]-gw[r][1]-gw[r][2])*(1.f/6.f);
            U[r*6+2] = (-gw[r][0]+gw[r][1]-gw[r][2])*(1.f/6.f);
            U[r*6+3] = gw[r][0]*(1.f/24.f) + gw[r][1]*(1.f/12.f) + gw[r][2]*(1.f/6.f);
            U[r*6+4] = gw[r][0]*(1.f/24.f) - gw[r][1]*(1.f/12.f) + gw[r][2]*(1.f/6.f);
            U[r*6+5] = gw[r][2];
        }
    }
    #pragma unroll
    for (int tp = 0; tp < 36; tp++){
        uint32_t hp, lp;
        split2(Ua[tp], Ub[tp], hp, lp);
        g_uwH[(long)tp*C_*96 + o*96 + j] = hp;
        g_uwL[(long)tp*C_*96 + o*96 + j] = lp;
    }
}

// ---------------- winograd input transform (ALU-lean, coalesced) ----------------
__global__ void __launch_bounds__(256) wino_in_kernel(const float* __restrict__ y){
    __shared__ float inS[8][6][132];
    const int TY  = blockIdx.x;
    const int ic0 = blockIdx.y * 8;
    const int b   = blockIdx.z;
    const int tid = threadIdx.x;
    const int wrp = tid >> 5, lane = tid & 31;
    {
        const int gy0 = 4*TY - 1;
        #pragma unroll
        for (int rr = 0; rr < 6; rr++){
            int rowid = wrp + rr * 8;
            int ic = rowid / 6, r = rowid % 6;
            int gy = gy0 + r;
            const float* src = y + ((long)(b*C_ + ic0 + ic))*HW_ + gy*WW_;
            bool rowok = (unsigned)gy < 128u;
            float* dst = &inS[ic][r][0];
            #pragma unroll
            for (int j = 0; j < 5; j++){
                int col = lane + j*32 - 1;
                if (j < 4 || col < 131){
                    float v = 0.f;
                    if (rowok && (unsigned)col < 128u) v = src[col];
                    if (col + 1 < 132) dst[col + 1] = v;
                }
            }
        }
    }
    __syncthreads();
    const int tx  = lane;
    const int icl = wrp;
    float vv[36];
    {
        float d[6][6];
        #pragma unroll
        for (int r = 0; r < 6; r++)
            #pragma unroll
            for (int c = 0; c < 6; c++)
                d[r][c] = inS[icl][r][4*tx + c];
        float t[6][6];
        #pragma unroll
        for (int c = 0; c < 6; c++){
            t[0][c] =  4.f*d[0][c] - 5.f*d[2][c] + d[4][c];
            t[1][c] = -4.f*d[1][c] - 4.f*d[2][c] + d[3][c] + d[4][c];
            t[2][c] =  4.f*d[1][c] - 4.f*d[2][c] - d[3][c] + d[4][c];
            t[3][c] = -2.f*d[1][c] - d[2][c] + 2.f*d[3][c] + d[4][c];
            t[4][c] =  2.f*d[1][c] - d[2][c] - 2.f*d[3][c] + d[4][c];
            t[5][c] =  4.f*d[1][c] - 5.f*d[3][c] + d[5][c];
        }
        #pragma unroll
        for (int r = 0; r < 6; r++){
            vv[r*6+0] =  4.f*t[r][0] - 5.f*t[r][2] + t[r][4];
            vv[r*6+1] = -4.f*t[r][1] - 4.f*t[r][2] + t[r][3] + t[r][4];
            vv[r*6+2] =  4.f*t[r][1] - 4.f*t[r][2] - t[r][3] + t[r][4];
            vv[r*6+3] = -2.f*t[r][1] - t[r][2] + 2.f*t[r][3] + t[r][4];
            vv[r*6+4] =  2.f*t[r][1] - t[r][2] - 2.f*t[r][3] + t[r][4];
            vv[r*6+5] =  4.f*t[r][1] - 5.f*t[r][3] + t[r][5];
        }
    }
    float* p = g_vw + (((long)(b*TAPS))*C_ + (ic0 + icl))*TPI + TY*32 + tx;
    #pragma unroll
    for (int tp = 0; tp < 36; tp++){
        *p = vv[tp];
        p += (long)C_ * TPI;
    }
}

// ---------------- winograd output transform ------------------------------------
__global__ void __launch_bounds__(128) wino_out_kernel(){
    const int tb = blockIdx.x, oc = blockIdx.y, b = blockIdx.z;
    const int tile = tb*128 + threadIdx.x;
    float m[36];
    const float* p = g_wm + (((long)(b*TAPS))*C_ + oc)*TPI + tile;
    #pragma unroll
    for (int tp = 0; tp < 36; tp++){
        m[tp] = *p;
        p += (long)C_ * TPI;
    }
    float t[4][6];
    #pragma unroll
    for (int c = 0; c < 6; c++){
        float m0=m[c], m1=m[6+c], m2=m[12+c], m3=m[18+c], m4=m[24+c], m5=m[30+c];
        t[0][c] = m0+m1+m2+m3+m4;
        t[1][c] = m1-m2+2.f*m3-2.f*m4;
        t[2][c] = m1+m2+4.f*m3+4.f*m4;
        t[3][c] = m1-m2+8.f*m3-8.f*m4+m5;
    }
    int ty = tile >> 5, tx = tile & 31;
    float* op = &g_q[((long)(b*C_ + oc))*HW_ + (4*ty)*WW_ + 4*tx];
    #pragma unroll
    for (int r = 0; r < 4; r++){
        float o0 = t[r][0]+t[r][1]+t[r][2]+t[r][3]+t[r][4];
        float o1 = t[r][1]-t[r][2]+2.f*t[r][3]-2.f*t[r][4];
        float o2 = t[r][1]+t[r][2]+4.f*t[r][3]+4.f*t[r][4];
        float o3 = t[r][1]-t[r][2]+8.f*t[r][3]-8.f*t[r][4]+t[r][5];
        *(float4*)&op[r*WW_] = make_float4(o0,o1,o2,o3);
    }
}

// ---------------- 3-term bf16 mma.sync GEMM, M128 x N96, 2 CTA/SM ---------------
// A smem layout: per row 176B = 4 x [16B hi block | 16B lo block] + 16B pad.
// hi k-segment j (8 bf16) at row*176 + j*32; lo at +16. v4 stores, ldsm-aligned.
#define AROWB 176
#define ABYTES (128 * AROWB)       // 22528
#define BROWB 80
#define BHB   (96 * BROWB)         // 7680
#define STG   (ABYTES + 2*BHB)     // 37888
#define TG_SMEM (3*STG)            // 113664

template<int MODE>
__global__ void __launch_bounds__(256, 2) mma_gemm_kernel(
    const float* __restrict__ A, long aBS, int aRow,
    const uint32_t* __restrict__ BH, const uint32_t* __restrict__ BL, long bBS,
    int bRow, int NG, float* __restrict__ Out, long oBS, int oRow)
{
    extern __shared__ char smem[];
    const uint32_t sb = s2u(smem);
    const int tid = threadIdx.x;
    const int b = blockIdx.z;
    const int pBase = blockIdx.x * 128;
    const int nBase = blockIdx.y * 96;
    const float* Ab = A + (long)b * aBS;
    const long bsel2 = (MODE == 2) ? (long)(b % TAPS) : (long)b;
    const uint32_t* BHb = BH + bsel2 * bBS + (long)nBase * bRow;
    const uint32_t* BLb = BL + bsel2 * bBS + (long)nBase * bRow;

    const int lane = tid & 31, wid = tid >> 5;
    const int wm = (wid & 3) * 32;        // 4 warps along M (128)
    const int wn = (wid >> 2) * 48;       // 2 warps along N (96)
    const int g8 = lane >> 2, tig = lane & 3;
    const uint32_t arow = (lane & 7) + ((lane >> 3) & 1) * 8;
    const uint32_t asel = (lane >> 4) & 1;         // k-segment select within fragment
    const uint32_t brow = (lane & 7) + ((lane >> 4) & 1) * 8;
    const uint32_t bcol = ((lane >> 3) & 1) * 4;
    const int am = tid & 127, akp = (tid >> 7) * 8;   // A: row, starting k-pair

    float acc[2][6][4];
    #pragma unroll
    for (int a = 0; a < 2; a++)
        #pragma unroll
        for (int n = 0; n < 6; n++)
            #pragma unroll
            for (int c = 0; c < 4; c++) acc[a][n][c] = 0.f;

    float rbuf[2][16];
    auto ldA = [&](int g, float* rb){
        const float* base = Ab + pBase + am + (long)(g*32 + 2*akp) * aRow;
        #pragma unroll
        for (int j = 0; j < 8; j++){
            rb[2*j]   = __ldg(base);
            rb[2*j+1] = __ldg(base + aRow);
            base += 2L * aRow;
        }
    };
    auto stA = [&](int sel, const float* rb){
        uint32_t abuf = sb + (uint32_t)sel*STG + am*AROWB;
        #pragma unroll
        for (int blk = 0; blk < 2; blk++){
            uint32_t h[4], l[4];
            #pragma unroll
            for (int j = 0; j < 4; j++)
                split2(rb[blk*8 + 2*j], rb[blk*8 + 2*j + 1], h[j], l[j]);
            uint32_t base = abuf + ((akp >> 2) + blk) * 32;
            asm volatile("st.shared.v4.b32 [%0], {%1,%2,%3,%4};"
                         :: "r"(base), "r"(h[0]), "r"(h[1]), "r"(h[2]), "r"(h[3]));
            asm volatile("st.shared.v4.b32 [%0], {%1,%2,%3,%4};"
                         :: "r"(base + 16), "r"(l[0]), "r"(l[1]), "r"(l[2]), "r"(l[3]));
        }
    };
    auto stageB = [&](int g, int sel){
        const uint32_t bhbuf = sb + sel * STG + ABYTES;
        const uint32_t blbuf = bhbuf + BHB;
        #pragma unroll
        for (int i = 0; i < 3; i++){
            int idx = tid + i * 256;            // 768 = 96 n x 4 c16 x 2 arr
            int n = idx >> 3, r = idx & 7;
            int arr = r >> 2, c16 = r & 3;
            uint32_t sa = (arr ? blbuf : bhbuf) + n * BROWB + c16 * 16;
            const uint32_t* gp = (arr ? BLb : BHb) + (long)n * bRow + g * 16 + c16 * 4;
            asm volatile("cp.async.cg.shared.global [%0], [%1], 16;" :: "r"(sa), "l"(gp) : "memory");
        }
        asm volatile("cp.async.commit_group;" ::: "memory");
    };

    ldA(0, rbuf[0]);
    stageB(0, 0);
    ldA(1, rbuf[1]);
    stageB(1, 1);
    stA(0, rbuf[0]);
    for (int g = 0; g < NG; g++){
        const int sel = g % 3;
        if (g + 1 < NG) stA((g + 1) % 3, rbuf[(g + 1) % 2]);
        if (g + 2 < NG){
            ldA(g + 2, rbuf[(g + 2) % 2]);
            stageB(g + 2, (g + 2) % 3);
            asm volatile("cp.async.wait_group 2;" ::: "memory");
        } else if (g + 1 < NG){
            asm volatile("cp.async.wait_group 1;" ::: "memory");
        } else {
            asm volatile("cp.async.wait_group 0;" ::: "memory");
        }
        __syncthreads();
        const uint32_t abase  = sb + sel * STG;
        const uint32_t bhbase = abase + ABYTES;
        const uint32_t blbase = bhbase + BHB;
        #pragma unroll
        for (int ks = 0; ks < 2; ks++){
            uint32_t bh[6][2], bl[6][2];
            #pragma unroll
            for (int j = 0; j < 3; j++){
                uint32_t off = (uint32_t)((wn + j * 16 + brow) * BROWB + (ks * 8 + bcol) * 4);
                ldsm4(bh[2*j][0], bh[2*j][1], bh[2*j+1][0], bh[2*j+1][1], bhbase + off);
                ldsm4(bl[2*j][0], bl[2*j][1], bl[2*j+1][0], bl[2*j+1][1], blbase + off);
            }
            #pragma unroll
            for (int mt = 0; mt < 2; mt++){
                uint32_t hoff = abase + (wm + mt * 16 + arow) * AROWB
                              + (2 * ks + asel) * 32;
                uint32_t ah0, ah1, ah2, ah3, al0, al1, al2, al3;
                ldsm4(ah0, ah1, ah2, ah3, hoff);
                ldsm4(al0, al1, al2, al3, hoff + 16);
                #pragma unroll
                for (int nt = 0; nt < 6; nt++){
                    asm volatile(
                        "mma.sync.aligned.m16n8k16.row.col.f32.bf16.bf16.f32 "
                        "{%0,%1,%2,%3}, {%4,%5,%6,%7}, {%8,%9}, {%0,%1,%2,%3};"
                        : "+f"(acc[mt][nt][0]), "+f"(acc[mt][nt][1]),
                          "+f"(acc[mt][nt][2]), "+f"(acc[mt][nt][3])
                        : "r"(ah0), "r"(ah1), "r"(ah2), "r"(ah3),
                          "r"(bh[nt][0]), "r"(bh[nt][1]));
                    asm volatile(
                        "mma.sync.aligned.m16n8k16.row.col.f32.bf16.bf16.f32 "
                        "{%0,%1,%2,%3}, {%4,%5,%6,%7}, {%8,%9}, {%0,%1,%2,%3};"
                        : "+f"(acc[mt][nt][0]), "+f"(acc[mt][nt][1]),
                          "+f"(acc[mt][nt][2]), "+f"(acc[mt][nt][3])
                        : "r"(ah0), "r"(ah1), "r"(ah2), "r"(ah3),
                          "r"(bl[nt][0]), "r"(bl[nt][1]));
                    asm volatile(
                        "mma.sync.aligned.m16n8k16.row.col.f32.bf16.bf16.f32 "
                        "{%0,%1,%2,%3}, {%4,%5,%6,%7}, {%8,%9}, {%0,%1,%2,%3};"
                        : "+f"(acc[mt][nt][0]), "+f"(acc[mt][nt][1]),
                          "+f"(acc[mt][nt][2]), "+f"(acc[mt][nt][3])
                        : "r"(al0), "r"(al1), "r"(al2), "r"(al3),
                          "r"(bh[nt][0]), "r"(bh[nt][1]));
                }
            }
        }
        __syncthreads();
    }

    float* Cs = (float*)smem;
    #pragma unroll
    for (int mt = 0; mt < 2; mt++)
        #pragma unroll
        for (int nt = 0; nt < 6; nt++){
            int m0 = wm + mt * 16 + g8;
            int n0 = wn + nt * 8 + tig * 2;
            Cs[n0 * 132 + m0]           = acc[mt][nt][0];
            Cs[(n0 + 1) * 132 + m0]     = acc[mt][nt][1];
            Cs[n0 * 132 + m0 + 8]       = acc[mt][nt][2];
            Cs[(n0 + 1) * 132 + m0 + 8] = acc[mt][nt][3];
        }
    __syncthreads();
    float* Ob = Out + (long)b * oBS;
    #pragma unroll
    for (int i = 0; i < 12; i++){
        int idx = tid + i * 256;
        int n = idx >> 5, c4 = idx & 31;
        *(float4*)&Ob[(long)(nBase + n) * oRow + pBase + c4 * 4] =
            *(float4*)&Cs[n * 132 + c4 * 4];
    }
}

// ---------------- depthwise 3x3, smem-tiled ------------------------------------
__global__ void __launch_bounds__(256) dw_kernel(const float* __restrict__ dww) {
    __shared__ float tile[34][128];
    __shared__ float ws[9];
    const int b = blockIdx.z, c = blockIdx.y, rb = blockIdx.x * 32;
    const int tid = threadIdx.x;
    if (tid < 9) ws[tid] = dww[c * 9 + tid];
    const float* ip = &g_kv0[((long)(b * C2_ + c)) * HW_];
    for (int idx = tid; idx < 34 * 128; idx += 256){
        int lr = idx >> 7, col = idx & 127;
        int gy = rb - 1 + lr;
        tile[lr][col] = ((unsigned)gy < 128u) ? ip[gy * 128 + col] : 0.f;
    }
    __syncthreads();
    const int lrow = tid >> 3, c0 = (tid & 7) * 16;
    float wv[3][18];
    #pragma unroll
    for (int dy = 0; dy < 3; dy++){
        const float* tr = tile[lrow + dy];
        wv[dy][0]  = (c0 > 0) ? tr[c0 - 1] : 0.f;
        #pragma unroll
        for (int q = 0; q < 4; q++){
            float4 v = *(const float4*)&tr[c0 + q * 4];
            wv[dy][1 + q*4] = v.x; wv[dy][2 + q*4] = v.y;
            wv[dy][3 + q*4] = v.z; wv[dy][4 + q*4] = v.w;
        }
        wv[dy][17] = (c0 + 16 < 128) ? tr[c0 + 16] : 0.f;
    }
    float o[16];
    #pragma unroll
    for (int cc = 0; cc < 16; cc++){
        float a = 0.f;
        #pragma unroll
        for (int dy = 0; dy < 3; dy++)
            #pragma unroll
            for (int dx = 0; dx < 3; dx++)
                a = fmaf(ws[dy * 3 + dx], wv[dy][cc + dx], a);
        o[cc] = a;
    }
    float* op = &g_kvd[((long)(b * C2_ + c)) * HW_ + (rb + lrow) * 128 + c0];
    #pragma unroll
    for (int q = 0; q < 4; q++)
        *(float4*)&op[q * 4] = make_float4(o[q*4], o[q*4+1], o[q*4+2], o[q*4+3]);
}

// ---------------- QK^T partial dots + fused sumsq partials ---------------------
__global__ __launch_bounds__(256) void attn_dot_kernel() {
    __shared__ float qS[CH_ * 68];
    __shared__ float kS[CH_ * 68];
    __shared__ float redq[8][12], redk[8][12];
    const int sl = blockIdx.x, h = blockIdx.y, b = blockIdx.z;
    const int tid = threadIdx.x;
    const int c0 = (tid >> 4) * 3, d0 = (tid & 15) * 3;
    float acc[3][3] = {};
    float sqq[12] = {}, sqk[12] = {};
    const float* qbase = &g_q[((long)(b * C_) + h * CH_) * HW_];
    const float* kbase = &g_kvd[((long)(b * C2_) + h * CH_) * HW_];
    const int n0 = sl * (HW_ / NSLICE);
    for (int chn = 0; chn < HW_ / NSLICE; chn += 64) {
        #pragma unroll
        for (int i = 0; i < 12; i++){
            int idx = tid + i * 256;
            int r = idx >> 6, col = idx & 63;
            float vq = qbase[(long)r * HW_ + n0 + chn + col];
            float vk = kbase[(long)r * HW_ + n0 + chn + col];
            qS[r * 68 + col] = vq; kS[r * 68 + col] = vk;
            sqq[i] = fmaf(vq, vq, sqq[i]);
            sqk[i] = fmaf(vk, vk, sqk[i]);
        }
        __syncthreads();
        #pragma unroll
        for (int n = 0; n < 64; n += 4) {
            float4 qv[3], kv[3];
            #pragma unroll
            for (int i = 0; i < 3; i++) qv[i] = *(const float4*)&qS[(c0 + i) * 68 + n];
            #pragma unroll
            for (int i = 0; i < 3; i++) kv[i] = *(const float4*)&kS[(d0 + i) * 68 + n];
            #pragma unroll
            for (int i = 0; i < 3; i++)
                #pragma unroll
                for (int j = 0; j < 3; j++) {
                    acc[i][j] = fmaf(qv[i].x, kv[j].x, acc[i][j]);
                    acc[i][j] = fmaf(qv[i].y, kv[j].y, acc[i][j]);
                    acc[i][j] = fmaf(qv[i].z, kv[j].z, acc[i][j]);
                    acc[i][j] = fmaf(qv[i].w, kv[j].w, acc[i][j]);
                }
        }
        __syncthreads();
    }
    const int w = tid >> 5;
    #pragma unroll
    for (int i = 0; i < 12; i++){
        float vq = sqq[i], vk = sqk[i];
        #pragma unroll
        for (int off = 16; off; off >>= 1){
            vq += __shfl_xor_sync(0xffffffffu, vq, off);
            vk += __shfl_xor_sync(0xffffffffu, vk, off);
        }
        if ((tid & 31) == 0){ redq[w][i] = vq; redk[w][i] = vk; }
    }
    __syncthreads();
    if (tid < CH_){
        int r0 = tid & 3, ii = tid >> 2;
        float sq = redq[2*r0][ii] + redq[2*r0+1][ii];
        float sk = redk[2*r0][ii] + redk[2*r0+1][ii];
        g_nsq[((long)sl * B_ + b) * C_ + h * CH_ + tid] = sq;
        g_nsq[(long)NSLICE * B_ * C_ + ((long)sl * B_ + b) * C_ + h * CH_ + tid] = sk;
    }
    float* outp = &g_part[(((long)sl * B_ + b) * HEADS_ + h) * CH_ * CH_];
    #pragma unroll
    for (int i = 0; i < 3; i++)
        #pragma unroll
        for (int j = 0; j < 3; j++)
            outp[(c0 + i) * CH_ + d0 + j] = acc[i][j];
}

// ---------------- scale + softmax ---------------------------------------------
__global__ void softmax_kernel(const float* __restrict__ temp) {
    __shared__ float ikS[CH_];
    const int h = blockIdx.x & 3, b = blockIdx.x >> 2;
    const int c = threadIdx.x;
    if (c < CH_){
        float s = 0.f;
        for (int sl = 0; sl < NSLICE; sl++)
            s += g_nsq[(long)NSLICE * B_ * C_ + ((long)sl * B_ + b) * C_ + h * CH_ + c];
        ikS[c] = 1.0f / fmaxf(sqrtf(s), 1e-12f);
    }
    __syncthreads();
    if (c >= CH_) return;
    float sq = 0.f;
    for (int sl = 0; sl < NSLICE; sl++)
        sq += g_nsq[((long)sl * B_ + b) * C_ + h * CH_ + c];
    const float iq = 1.0f / fmaxf(sqrtf(sq), 1e-12f);
    const float t = temp[h] * logf((float)CH_);
    float row[CH_];
    float m = -1e30f;
    for (int d = 0; d < CH_; d++) {
        float s = 0.f;
        for (int sl = 0; sl < NSLICE; sl++)
            s += g_part[(((long)sl * B_ + b) * HEADS_ + h) * CH_ * CH_ + c * CH_ + d];
        row[d] = s * iq * ikS[d] * t;
        m = fmaxf(m, row[d]);
    }
    float sum = 0.f;
    for (int d = 0; d < CH_; d++) {
        row[d] = expf(row[d] - m);
        sum += row[d];
    }
    float inv = 1.0f / sum;
    for (int d = 0; d < CH_; d++)
        g_attn[((b * HEADS_ + h) * CH_ + c) * CH_ + d] = row[d] * inv;
}

// ---------------- launch ------------------------------------------------------
extern "C" void kernel_launch(void* const* d_in, const int* in_sizes, int n_in,
                              void* d_out, int out_size) {
    const float* x       = (const float*)d_in[0];
    const float* y       = (const float*)d_in[1];
    const float* kv_w    = (const float*)d_in[2];
    const float* kv_dw_w = (const float*)d_in[3];
    const float* q_w     = (const float*)d_in[4];
    const float* q_dw_w  = (const float*)d_in[5];
    const float* proj_w  = (const float*)d_in[6];
    const float* temp    = (const float*)d_in[7];
    float* out = (float*)d_out;

    void *p_kv0, *p_kvd, *p_q, *p_kwh, *p_kwl, *p_mwh, *p_mwl;
    void *p_uwh, *p_uwl, *p_vw, *p_wm;
    cudaGetSymbolAddress(&p_kv0, g_kv0);
    cudaGetSymbolAddress(&p_kvd, g_kvd);
    cudaGetSymbolAddress(&p_q,   g_q);
    cudaGetSymbolAddress(&p_kwh, g_kvwH); cudaGetSymbolAddress(&p_kwl, g_kvwL);
    cudaGetSymbolAddress(&p_mwh, g_mwH);  cudaGetSymbolAddress(&p_mwl, g_mwL);
    cudaGetSymbolAddress(&p_uwh, g_uwH);  cudaGetSymbolAddress(&p_uwl, g_uwL);
    cudaGetSymbolAddress(&p_vw,  g_vw);   cudaGetSymbolAddress(&p_wm,  g_wm);

    cudaFuncSetAttribute(mma_gemm_kernel<0>, cudaFuncAttributeMaxDynamicSharedMemorySize, TG_SMEM);
    cudaFuncSetAttribute(mma_gemm_kernel<2>, cudaFuncAttributeMaxDynamicSharedMemorySize, TG_SMEM);

    prep_qw_kernel<<<dim3(C_, 3), 192>>>(q_dw_w, q_w);                                 // #1
    wino_wt_kernel<<<C_, 96>>>();                                                      // #2
    wino_in_kernel<<<dim3(32, 24, B_), 256>>>(y);                                      // #3

    // winograd batched per-tap GEMM (N=96 x2)                    — launch #4 (ncu slot)
    mma_gemm_kernel<2><<<dim3(TPI / 128, 2, B_ * TAPS), 256, TG_SMEM>>>(
        (const float*)p_vw, (long)C_ * TPI, TPI,
        (const uint32_t*)p_uwh, (const uint32_t*)p_uwl, (long)C_ * 96, 96, 6,
        (float*)p_wm, (long)C_ * TPI, TPI);

    prep_kvw_kernel<<<(C2_ * 96) / 256, 256>>>(kv_w);                                  // #5

    // kv 1x1: N=384 as 4 chunks of 96                                                 // #6
    mma_gemm_kernel<0><<<dim3(HW_ / 128, 4, B_), 256, TG_SMEM>>>(
        x, (long)C_ * HW_, HW_,
        (const uint32_t*)p_kwh, (const uint32_t*)p_kwl, 0L, 96, 6,
        (float*)p_kv0, (long)C2_ * HW_, HW_);

    dw_kernel<<<dim3(HH_ / 32, C2_, B_), 256>>>(kv_dw_w);                              // #7
    wino_out_kernel<<<dim3(TPI / 128, C_, B_), 128>>>();                               // #8

    attn_dot_kernel<<<dim3(NSLICE, HEADS_, B_), 256>>>();                              // #9
    softmax_kernel<<<B_ * HEADS_, 64>>>(temp);                                         // #10
    prep_mw_kernel<<<(B_ * C_ * 96) / 256, 256>>>(proj_w);                             // #11

    // fused (proj @ attn) @ v -> out : N=192 as 2 chunks of 96                        // #12
    mma_gemm_kernel<0><<<dim3(HW_ / 128, 2, B_), 256, TG_SMEM>>>(
        (const float*)p_kvd + (long)C_ * HW_, (long)C2_ * HW_, HW_,
        (const uint32_t*)p_mwh, (const uint32_t*)p_mwl, (long)C_ * 96, 96, 6,
        out, (long)C_ * HW_, HW_);
}